// round 2
// baseline (speedup 1.0000x reference)
#include <cuda_runtime.h>

#define N_NODES  100000
#define F_IN     512
#define HIDDEN   64
#define MAX_E    3200000
#define SCAN_BLK 1024
#define NSCAN    98                      // 98*1024 = 100352 >= N_NODES+1
#define NPAD     (NSCAN * SCAN_BLK)

#define TM 128
#define KC 64
#define WX 128
#define WW 64
#define NTHREADS 256

// ---- static device scratch (no runtime allocation) ----
__device__ float               g_logits[(long long)N_NODES * HIDDEN];   // 25.6MB
__device__ unsigned            g_cnt[NPAD];
__device__ unsigned            g_rowstart[NPAD];
__device__ unsigned            g_cursor[NPAD];
__device__ unsigned            g_part[128];
__device__ unsigned            g_partscan[128];
__device__ unsigned long long  g_meta[MAX_E];                           // 25.6MB (val<<32 | col)

// ---- packed f32x2 helpers (sm_100+ PTX) ----
#define PACK2F(d, x)    asm("mov.b64 %0, {%1, %1};" : "=l"(d) : "r"(__float_as_uint(x)))
#define PACK2(d, a, b)  asm("mov.b64 %0, {%1, %2};" : "=l"(d) : "r"(__float_as_uint(a)), "r"(__float_as_uint(b)))
#define UNPACK2(lo, hi, s) asm("mov.b64 {%0, %1}, %2;" : "=r"(lo), "=r"(hi) : "l"(s))
#define FMA2(acc, a, b) asm("fma.rn.f32x2 %0, %1, %2, %0;" : "+l"(acc) : "l"(a), "l"(b))

#define GEMM_TILE_STEP(ACC, XR, WR) do {                                       \
    ulonglong2 _xa = *(const ulonglong2*)(XR);                                 \
    ulonglong2 _xb = *(const ulonglong2*)((XR) + 4);                           \
    float4 _wv = *(const float4*)(WR);                                         \
    unsigned long long _w0, _w1, _w2, _w3;                                     \
    PACK2F(_w0, _wv.x); PACK2F(_w1, _wv.y); PACK2F(_w2, _wv.z); PACK2F(_w3, _wv.w); \
    FMA2(ACC[0][0], _xa.x, _w0); FMA2(ACC[0][1], _xa.x, _w1);                  \
    FMA2(ACC[0][2], _xa.x, _w2); FMA2(ACC[0][3], _xa.x, _w3);                  \
    FMA2(ACC[1][0], _xa.y, _w0); FMA2(ACC[1][1], _xa.y, _w1);                  \
    FMA2(ACC[1][2], _xa.y, _w2); FMA2(ACC[1][3], _xa.y, _w3);                  \
    FMA2(ACC[2][0], _xb.x, _w0); FMA2(ACC[2][1], _xb.x, _w1);                  \
    FMA2(ACC[2][2], _xb.x, _w2); FMA2(ACC[2][3], _xb.x, _w3);                  \
    FMA2(ACC[3][0], _xb.y, _w0); FMA2(ACC[3][1], _xb.y, _w1);                  \
    FMA2(ACC[3][2], _xb.y, _w2); FMA2(ACC[3][3], _xb.y, _w3);                  \
  } while (0)

// ============================ fused MLP =====================================
__global__ __launch_bounds__(NTHREADS, 2) void mlp_kernel(
    const float* __restrict__ X,
    const float* __restrict__ W1, const float* __restrict__ b1,
    const float* __restrict__ W2, const float* __restrict__ b2)
{
  __shared__ float Xs[KC * WX];
  __shared__ float Ws[KC * WW];

  const int tid  = threadIdx.x;
  const int cg   = tid & 15;
  const int rg   = tid >> 4;
  const int row0 = blockIdx.x * TM;

  unsigned long long acc[4][4];
#pragma unroll
  for (int p = 0; p < 4; ++p)
#pragma unroll
    for (int j = 0; j < 4; ++j) acc[p][j] = 0ULL;

  for (int ch = 0; ch < F_IN / KC; ++ch) {
    const int kc = ch * KC;
#pragma unroll
    for (int it = 0; it < (TM * KC / 4) / NTHREADS; ++it) {
      int idx = it * NTHREADS + tid;
      int a   = idx & 3;
      int m   = (idx >> 2) & 127;
      int khi = idx >> 9;
      int k4  = khi * 4 + a;
      int gm  = row0 + m;
      float4 v = make_float4(0.f, 0.f, 0.f, 0.f);
      if (gm < N_NODES)
        v = *(const float4*)(X + (long long)gm * F_IN + kc + k4 * 4);
      Xs[(k4 * 4 + 0) * WX + m] = v.x;
      Xs[(k4 * 4 + 1) * WX + m] = v.y;
      Xs[(k4 * 4 + 2) * WX + m] = v.z;
      Xs[(k4 * 4 + 3) * WX + m] = v.w;
    }
#pragma unroll
    for (int it = 0; it < (KC * HIDDEN / 4) / NTHREADS; ++it) {
      int idx = it * NTHREADS + tid;
      int k  = idx >> 4;
      int n4 = (idx & 15) * 4;
      *(float4*)(Ws + k * WW + n4) =
          *(const float4*)(W1 + (long long)(kc + k) * HIDDEN + n4);
    }
    __syncthreads();
#pragma unroll 8
    for (int kk = 0; kk < KC; ++kk) {
      const float* xr = Xs + kk * WX + rg * 8;
      const float* wr = Ws + kk * WW + cg * 4;
      GEMM_TILE_STEP(acc, xr, wr);
    }
    __syncthreads();
  }

  {
    float4 b1v = *(const float4*)(b1 + cg * 4);
    float bb[4] = {b1v.x, b1v.y, b1v.z, b1v.w};
#pragma unroll
    for (int p = 0; p < 4; ++p)
#pragma unroll
      for (int j = 0; j < 4; ++j) {
        unsigned lo, hi;
        UNPACK2(lo, hi, acc[p][j]);
        float flo = fmaxf(__uint_as_float(lo) + bb[j], 0.f);
        float fhi = fmaxf(__uint_as_float(hi) + bb[j], 0.f);
        unsigned long long pr;
        PACK2(pr, flo, fhi);
        *(unsigned long long*)(Xs + (cg * 4 + j) * WX + rg * 8 + 2 * p) = pr;
      }
#pragma unroll
    for (int it = 0; it < (HIDDEN * HIDDEN / 4) / NTHREADS; ++it) {
      int idx = it * NTHREADS + tid;
      int k  = idx >> 4;
      int n4 = (idx & 15) * 4;
      *(float4*)(Ws + k * WW + n4) = *(const float4*)(W2 + k * HIDDEN + n4);
    }
  }
  __syncthreads();

  unsigned long long acc2[4][4];
#pragma unroll
  for (int p = 0; p < 4; ++p)
#pragma unroll
    for (int j = 0; j < 4; ++j) acc2[p][j] = 0ULL;
#pragma unroll 8
  for (int kk = 0; kk < HIDDEN; ++kk) {
    const float* xr = Xs + kk * WX + rg * 8;
    const float* wr = Ws + kk * WW + cg * 4;
    GEMM_TILE_STEP(acc2, xr, wr);
  }

  float4 b2v = *(const float4*)(b2 + cg * 4);
#pragma unroll
  for (int p = 0; p < 4; ++p) {
    unsigned lo0, hi0, lo1, hi1, lo2, hi2, lo3, hi3;
    UNPACK2(lo0, hi0, acc2[p][0]);
    UNPACK2(lo1, hi1, acc2[p][1]);
    UNPACK2(lo2, hi2, acc2[p][2]);
    UNPACK2(lo3, hi3, acc2[p][3]);
    int gm0 = row0 + rg * 8 + 2 * p;
    if (gm0 < N_NODES) {
      float4 r;
      r.x = __uint_as_float(lo0) + b2v.x;
      r.y = __uint_as_float(lo1) + b2v.y;
      r.z = __uint_as_float(lo2) + b2v.z;
      r.w = __uint_as_float(lo3) + b2v.w;
      *(float4*)(g_logits + (long long)gm0 * HIDDEN + cg * 4) = r;
    }
    int gm1 = gm0 + 1;
    if (gm1 < N_NODES) {
      float4 r;
      r.x = __uint_as_float(hi0) + b2v.x;
      r.y = __uint_as_float(hi1) + b2v.y;
      r.z = __uint_as_float(hi2) + b2v.z;
      r.w = __uint_as_float(hi3) + b2v.w;
      *(float4*)(g_logits + (long long)gm1 * HIDDEN + cg * 4) = r;
    }
  }
}

// ============================ CSR build =====================================
__global__ void zero_cnt_kernel()
{
  int i = blockIdx.x * blockDim.x + threadIdx.x;
  if (i < NPAD) g_cnt[i] = 0u;
}

__global__ void hist_kernel(const int* __restrict__ rows, int E)
{
  int i = blockIdx.x * blockDim.x + threadIdx.x;
  if (i < E) atomicAdd(&g_cnt[rows[i]], 1u);
}

// per-block sums of 1024-element chunks
__global__ __launch_bounds__(SCAN_BLK) void scanA_kernel()
{
  __shared__ unsigned s[SCAN_BLK];
  int t = threadIdx.x;
  s[t] = g_cnt[blockIdx.x * SCAN_BLK + t];
  __syncthreads();
#pragma unroll
  for (int o = SCAN_BLK / 2; o > 0; o >>= 1) {
    if (t < o) s[t] += s[t + o];
    __syncthreads();
  }
  if (t == 0) g_part[blockIdx.x] = s[0];
}

// exclusive scan of the 98 partials (one block of 128)
__global__ __launch_bounds__(128) void scanB_kernel()
{
  __shared__ unsigned s[128];
  int t = threadIdx.x;
  s[t] = (t < NSCAN) ? g_part[t] : 0u;
  __syncthreads();
#pragma unroll
  for (int o = 1; o < 128; o <<= 1) {
    unsigned x = (t >= o) ? s[t - o] : 0u;
    __syncthreads();
    s[t] += x;
    __syncthreads();
  }
  g_partscan[t] = (t > 0) ? s[t - 1] : 0u;
}

// local exclusive scan + block offset -> rowstart & cursor
__global__ __launch_bounds__(SCAN_BLK) void scanC_kernel()
{
  __shared__ unsigned s[SCAN_BLK];
  int t = threadIdx.x;
  int gi = blockIdx.x * SCAN_BLK + t;
  s[t] = g_cnt[gi];
  __syncthreads();
#pragma unroll
  for (int o = 1; o < SCAN_BLK; o <<= 1) {
    unsigned x = (t >= o) ? s[t - o] : 0u;
    __syncthreads();
    s[t] += x;
    __syncthreads();
  }
  unsigned excl = ((t > 0) ? s[t - 1] : 0u) + g_partscan[blockIdx.x];
  g_rowstart[gi] = excl;
  g_cursor[gi]   = excl;
}

__global__ void place_kernel(const int* __restrict__ rows,
                             const int* __restrict__ cols,
                             const float* __restrict__ vals, int E)
{
  int i = blockIdx.x * blockDim.x + threadIdx.x;
  if (i < E) {
    int r = rows[i];
    unsigned pos = atomicAdd(&g_cursor[r], 1u);
    g_meta[pos] = ((unsigned long long)__float_as_uint(vals[i]) << 32) |
                  (unsigned)cols[i];
  }
}

// ============================ SpMM ==========================================
// one warp per row; lane owns output cols [2*lane, 2*lane+1]
__global__ __launch_bounds__(256) void spmm_kernel(float* __restrict__ out)
{
  const int lane = threadIdx.x & 31;
  const int warp = (blockIdx.x * blockDim.x + threadIdx.x) >> 5;
  const int nw   = (gridDim.x * blockDim.x) >> 5;

  for (int r = warp; r < N_NODES; r += nw) {
    unsigned s = g_rowstart[r];
    unsigned e = g_rowstart[r + 1];
    unsigned long long acc0 = 0ULL, acc1 = 0ULL;
    unsigned i = s;
    for (; i + 2 <= e; i += 2) {
      unsigned long long m0 = __ldg(g_meta + i);
      unsigned long long m1 = __ldg(g_meta + i + 1);
      unsigned c0 = (unsigned)m0, c1 = (unsigned)m1;
      float v0 = __uint_as_float((unsigned)(m0 >> 32));
      float v1 = __uint_as_float((unsigned)(m1 >> 32));
      unsigned long long p0 = *(const unsigned long long*)(g_logits + (long long)c0 * HIDDEN + 2 * lane);
      unsigned long long p1 = *(const unsigned long long*)(g_logits + (long long)c1 * HIDDEN + 2 * lane);
      unsigned long long vv0, vv1;
      PACK2F(vv0, v0); PACK2F(vv1, v1);
      FMA2(acc0, p0, vv0);
      FMA2(acc1, p1, vv1);
    }
    if (i < e) {
      unsigned long long m0 = __ldg(g_meta + i);
      unsigned c0 = (unsigned)m0;
      float v0 = __uint_as_float((unsigned)(m0 >> 32));
      unsigned long long p0 = *(const unsigned long long*)(g_logits + (long long)c0 * HIDDEN + 2 * lane);
      unsigned long long vv0;
      PACK2F(vv0, v0);
      FMA2(acc0, p0, vv0);
    }
    unsigned lo0, hi0, lo1, hi1;
    UNPACK2(lo0, hi0, acc0);
    UNPACK2(lo1, hi1, acc1);
    float2 res;
    res.x = __uint_as_float(lo0) + __uint_as_float(lo1);
    res.y = __uint_as_float(hi0) + __uint_as_float(hi1);
    *(float2*)(out + (long long)r * HIDDEN + 2 * lane) = res;
  }
}

// ============================ launch ========================================
extern "C" void kernel_launch(void* const* d_in, const int* in_sizes, int n_in,
                              void* d_out, int out_size)
{
  const float* X     = (const float*)d_in[0];
  const int*   erows = (const int*)  d_in[1];
  const int*   ecols = (const int*)  d_in[2];
  const float* evals = (const float*)d_in[3];
  const float* W1    = (const float*)d_in[4];
  const float* b1    = (const float*)d_in[5];
  const float* W2    = (const float*)d_in[6];
  const float* b2    = (const float*)d_in[7];
  float* out = (float*)d_out;
  const int E = in_sizes[1];

  // ---- CSR build ----
  zero_cnt_kernel<<<(NPAD + 255) / 256, 256>>>();
  hist_kernel<<<(E + 255) / 256, 256>>>(erows, E);
  scanA_kernel<<<NSCAN, SCAN_BLK>>>();
  scanB_kernel<<<1, 128>>>();
  scanC_kernel<<<NSCAN, SCAN_BLK>>>();
  place_kernel<<<(E + 255) / 256, 256>>>(erows, ecols, evals, E);

  // ---- fused MLP -> g_logits ----
  mlp_kernel<<<(N_NODES + TM - 1) / TM, NTHREADS>>>(X, W1, b1, W2, b2);

  // ---- SpMM: one warp per row, no output atomics ----
  spmm_kernel<<<(N_NODES / 8), 256>>>(out);
}

// round 4
// speedup vs baseline: 1.7689x; 1.7689x over previous
#include <cuda_runtime.h>

#define N_NODES 100000
#define F_IN    512
#define HIDDEN  64
#define TM      128
#define NBLK    ((N_NODES + TM - 1) / TM)   // 782

// smem layout: bf16 tiles, k-major [k][n], n-pitch padded to 72 bf16 = 144B
#define PITCH     144
#define OFF_W1HI  0
#define OFF_W1LO  73728                      // 512*144
#define OFF_W2HI  147456
#define OFF_W2LO  156672                     // +64*144
#define SMEM_TOTAL 165888

__device__ float g_logits[(long long)N_NODES * HIDDEN];   // 25.6MB

// ---- helpers ----
__device__ __forceinline__ unsigned smem_u32(const void* p) {
  unsigned a;
  asm("{ .reg .u64 t; cvta.to.shared.u64 t, %1; cvt.u32.u64 %0, t; }" : "=r"(a) : "l"(p));
  return a;
}
// split (x,y) into packed bf16x2 hi and lo: lo16 half = x, hi16 half = y
__device__ __forceinline__ void split2(float x, float y, unsigned &hi, unsigned &lo) {
  asm("cvt.rn.bf16x2.f32 %0, %1, %2;" : "=r"(hi) : "f"(y), "f"(x));
  float hx = __uint_as_float(hi << 16);
  float hy = __uint_as_float(hi & 0xFFFF0000u);
  asm("cvt.rn.bf16x2.f32 %0, %1, %2;" : "=r"(lo) : "f"(y - hy), "f"(x - hx));
}
__device__ __forceinline__ void ldmat4t(unsigned &r0, unsigned &r1, unsigned &r2,
                                        unsigned &r3, unsigned addr) {
  asm volatile("ldmatrix.sync.aligned.m8n8.x4.trans.shared.b16 {%0,%1,%2,%3}, [%4];"
               : "=r"(r0), "=r"(r1), "=r"(r2), "=r"(r3) : "r"(addr));
}
__device__ __forceinline__ void mma16816(float4 &c, unsigned a0, unsigned a1,
                                         unsigned a2, unsigned a3,
                                         unsigned b0, unsigned b1) {
  asm volatile("mma.sync.aligned.m16n8k16.row.col.f32.bf16.bf16.f32 "
               "{%0,%1,%2,%3}, {%4,%5,%6,%7}, {%8,%9}, {%0,%1,%2,%3};"
               : "+f"(c.x), "+f"(c.y), "+f"(c.z), "+f"(c.w)
               : "r"(a0), "r"(a1), "r"(a2), "r"(a3), "r"(b0), "r"(b1));
}

// ================= fused MLP via HMMA bf16x3 ================================
__global__ __launch_bounds__(256) void mlp_hmma(
    const float* __restrict__ X,
    const float* __restrict__ W1, const float* __restrict__ b1,
    const float* __restrict__ W2, const float* __restrict__ b2)
{
  extern __shared__ unsigned char sm[];
  const unsigned sb = smem_u32(sm);
  const int tid  = threadIdx.x;
  const int warp = tid >> 5;
  const unsigned lane = tid & 31;
  const int g  = lane >> 2;            // row group within fragment
  const int c2 = (lane & 3) * 2;       // col/k pair offset

  // ---- stage W1 hi/lo (once per CTA == once per SM) ----
  for (int i = tid; i < F_IN * 32; i += 256) {
    int k = i >> 5, pr = i & 31;
    float2 w = __ldg((const float2*)(W1 + k * 64 + pr * 2));
    unsigned hi, lo; split2(w.x, w.y, hi, lo);
    *(unsigned*)(sm + OFF_W1HI + k * PITCH + pr * 4) = hi;
    *(unsigned*)(sm + OFF_W1LO + k * PITCH + pr * 4) = lo;
  }
  for (int i = tid; i < HIDDEN * 32; i += 256) {
    int k = i >> 5, pr = i & 31;
    float2 w = __ldg((const float2*)(W2 + k * 64 + pr * 2));
    unsigned hi, lo; split2(w.x, w.y, hi, lo);
    *(unsigned*)(sm + OFF_W2HI + k * PITCH + pr * 4) = hi;
    *(unsigned*)(sm + OFF_W2LO + k * PITCH + pr * 4) = lo;
  }
  // biases per lane-column
  float2 b1p[8], b2p[8];
#pragma unroll
  for (int j = 0; j < 8; ++j) {
    b1p[j] = __ldg((const float2*)(b1 + 8 * j + c2));
    b2p[j] = __ldg((const float2*)(b2 + 8 * j + c2));
  }
  __syncthreads();

  // ldmatrix per-lane address offset (matrix id = lane>>3, row = lane&7)
  const int mid = lane >> 3, mrow = lane & 7;
  const unsigned loff = (unsigned)(((mid & 1) * 8 + mrow) * PITCH + (mid >> 1) * 16);
  const unsigned bW1h = sb + OFF_W1HI + loff;
  const unsigned bW1l = sb + OFF_W1LO + loff;
  const unsigned bW2h = sb + OFF_W2HI + loff;
  const unsigned bW2l = sb + OFF_W2LO + loff;

  for (int blk = blockIdx.x; blk < NBLK; blk += gridDim.x) {
    const int r0 = blk * TM + warp * 16 + g;
    const int r1 = r0 + 8;
    const bool v0 = r0 < N_NODES, v1 = r1 < N_NODES;
    const float* px0 = X + (long long)r0 * F_IN + c2;
    const float* px1 = X + (long long)r1 * F_IN + c2;

    float4 acc[8];
#pragma unroll
    for (int j = 0; j < 8; ++j) acc[j] = make_float4(0.f, 0.f, 0.f, 0.f);

    const float2 z2 = make_float2(0.f, 0.f);
    float2 cx00 = v0 ? __ldg((const float2*)px0)       : z2;
    float2 cx01 = v0 ? __ldg((const float2*)(px0 + 8)) : z2;
    float2 cx10 = v1 ? __ldg((const float2*)px1)       : z2;
    float2 cx11 = v1 ? __ldg((const float2*)(px1 + 8)) : z2;

#pragma unroll 4
    for (int ks = 0; ks < 32; ++ks) {
      float2 n00 = z2, n01 = z2, n10 = z2, n11 = z2;
      if (ks < 31) {
        const float* q0 = px0 + (ks + 1) * 16;
        const float* q1 = px1 + (ks + 1) * 16;
        if (v0) { n00 = __ldg((const float2*)q0); n01 = __ldg((const float2*)(q0 + 8)); }
        if (v1) { n10 = __ldg((const float2*)q1); n11 = __ldg((const float2*)(q1 + 8)); }
      }
      // A fragments: a0=(g,klo) a1=(g+8,klo) a2=(g,khi) a3=(g+8,khi)
      unsigned aH0, aL0, aH1, aL1, aH2, aL2, aH3, aL3;
      split2(cx00.x, cx00.y, aH0, aL0);
      split2(cx10.x, cx10.y, aH1, aL1);
      split2(cx01.x, cx01.y, aH2, aL2);
      split2(cx11.x, cx11.y, aH3, aL3);

#pragma unroll
      for (int jj = 0; jj < 4; ++jj) {
        unsigned h0, h1, h2, h3, l0, l1, l2, l3;
        ldmat4t(h0, h1, h2, h3, bW1h + ks * (16 * PITCH) + jj * 32);
        ldmat4t(l0, l1, l2, l3, bW1l + ks * (16 * PITCH) + jj * 32);
        mma16816(acc[2 * jj],     aH0, aH1, aH2, aH3, h0, h1);
        mma16816(acc[2 * jj],     aH0, aH1, aH2, aH3, l0, l1);
        mma16816(acc[2 * jj],     aL0, aL1, aL2, aL3, h0, h1);
        mma16816(acc[2 * jj + 1], aH0, aH1, aH2, aH3, h2, h3);
        mma16816(acc[2 * jj + 1], aH0, aH1, aH2, aH3, l2, l3);
        mma16816(acc[2 * jj + 1], aL0, aL1, aL2, aL3, h2, h3);
      }
      cx00 = n00; cx01 = n01; cx10 = n10; cx11 = n11;
    }

    // ---- epilogue 1: h = relu(acc + b1)  ->  GEMM2 A fragments (registers) ----
    unsigned A2h[4][4], A2l[4][4];
#pragma unroll
    for (int j = 0; j < 8; ++j) {
      float x = fmaxf(acc[j].x + b1p[j].x, 0.f);
      float y = fmaxf(acc[j].y + b1p[j].y, 0.f);
      float z = fmaxf(acc[j].z + b1p[j].x, 0.f);
      float w = fmaxf(acc[j].w + b1p[j].y, 0.f);
      unsigned h0, l0, h1, l1;
      split2(x, y, h0, l0);
      split2(z, w, h1, l1);
      int kk = j >> 1, s = j & 1;
      A2h[kk][2 * s] = h0; A2h[kk][2 * s + 1] = h1;
      A2l[kk][2 * s] = l0; A2l[kk][2 * s + 1] = l1;
    }

    // ---- GEMM2: logits = h @ W2 ----
    float4 acc2[8];
#pragma unroll
    for (int j = 0; j < 8; ++j) acc2[j] = make_float4(0.f, 0.f, 0.f, 0.f);
#pragma unroll
    for (int kk = 0; kk < 4; ++kk) {
#pragma unroll
      for (int jj = 0; jj < 4; ++jj) {
        unsigned h0, h1, h2, h3, l0, l1, l2, l3;
        ldmat4t(h0, h1, h2, h3, bW2h + kk * (16 * PITCH) + jj * 32);
        ldmat4t(l0, l1, l2, l3, bW2l + kk * (16 * PITCH) + jj * 32);
        mma16816(acc2[2 * jj],     A2h[kk][0], A2h[kk][1], A2h[kk][2], A2h[kk][3], h0, h1);
        mma16816(acc2[2 * jj],     A2h[kk][0], A2h[kk][1], A2h[kk][2], A2h[kk][3], l0, l1);
        mma16816(acc2[2 * jj],     A2l[kk][0], A2l[kk][1], A2l[kk][2], A2l[kk][3], h0, h1);
        mma16816(acc2[2 * jj + 1], A2h[kk][0], A2h[kk][1], A2h[kk][2], A2h[kk][3], h2, h3);
        mma16816(acc2[2 * jj + 1], A2h[kk][0], A2h[kk][1], A2h[kk][2], A2h[kk][3], l2, l3);
        mma16816(acc2[2 * jj + 1], A2l[kk][0], A2l[kk][1], A2l[kk][2], A2l[kk][3], h2, h3);
      }
    }

    // ---- epilogue 2: + b2, store ----
#pragma unroll
    for (int j = 0; j < 8; ++j) {
      if (v0) {
        float2 o = make_float2(acc2[j].x + b2p[j].x, acc2[j].y + b2p[j].y);
        *(float2*)(g_logits + (long long)r0 * HIDDEN + 8 * j + c2) = o;
      }
      if (v1) {
        float2 o = make_float2(acc2[j].z + b2p[j].x, acc2[j].w + b2p[j].y);
        *(float2*)(g_logits + (long long)r1 * HIDDEN + 8 * j + c2) = o;
      }
    }
  }
}

// ================= output zero + atomic scatter (round-1, best known) =======
__global__ void zero_kernel(float4* __restrict__ out, int n4)
{
  int stride = gridDim.x * blockDim.x;
  for (int i = blockIdx.x * blockDim.x + threadIdx.x; i < n4; i += stride)
    out[i] = make_float4(0.f, 0.f, 0.f, 0.f);
}

__global__ __launch_bounds__(256) void scatter_kernel(
    const int* __restrict__ rows, const int* __restrict__ cols,
    const float* __restrict__ vals, float* __restrict__ out, int E)
{
  const int lane = threadIdx.x & 31;
  const int l16  = lane & 15;
  const int half = lane >> 4;
  const int warp = (blockIdx.x * blockDim.x + threadIdx.x) >> 5;
  const int nw   = (gridDim.x * blockDim.x) >> 5;

  for (int base = warp * 2; base < E; base += nw * 2) {
    int e = base + half;
    if (e < E) {
      int   r = __ldg(rows + e);
      int   c = __ldg(cols + e);
      float v = __ldg(vals + e);
      float4 p = *(const float4*)(g_logits + (long long)c * HIDDEN + l16 * 4);
      float4 q = make_float4(p.x * v, p.y * v, p.z * v, p.w * v);
      float* dst = out + (long long)r * HIDDEN + l16 * 4;
      asm volatile("red.global.add.v4.f32 [%0], {%1, %2, %3, %4};"
                   :: "l"(dst), "f"(q.x), "f"(q.y), "f"(q.z), "f"(q.w)
                   : "memory");
    }
  }
}

// ================= launch ====================================================
extern "C" void kernel_launch(void* const* d_in, const int* in_sizes, int n_in,
                              void* d_out, int out_size)
{
  const float* X     = (const float*)d_in[0];
  const int*   erows = (const int*)  d_in[1];
  const int*   ecols = (const int*)  d_in[2];
  const float* evals = (const float*)d_in[3];
  const float* W1    = (const float*)d_in[4];
  const float* b1    = (const float*)d_in[5];
  const float* W2    = (const float*)d_in[6];
  const float* b2    = (const float*)d_in[7];
  float* out = (float*)d_out;
  const int E = in_sizes[1];

  cudaFuncSetAttribute(mlp_hmma, cudaFuncAttributeMaxDynamicSharedMemorySize, SMEM_TOTAL);

  zero_kernel<<<2048, 256>>>((float4*)out, out_size / 4);
  mlp_hmma<<<148, 256, SMEM_TOTAL>>>(X, W1, b1, W2, b2);
  scatter_kernel<<<2048, 256>>>(erows, ecols, evals, out, E);
}

// round 5
// speedup vs baseline: 2.1022x; 1.1884x over previous
#include <cuda_runtime.h>

#define N_NODES 100000
#define F_IN    512
#define HIDDEN  64
#define TM      128
#define NBLK    ((N_NODES + TM - 1) / TM)   // 782
#define SLOTS   64
#define MAX_E   3200000

// ---- static device scratch ----
__device__ float               g_logits[(long long)N_NODES * HIDDEN];       // 25.6MB
__device__ unsigned long long  g_meta[(long long)N_NODES * SLOTS];          // 51.2MB
__device__ unsigned            g_cnt[N_NODES];
__device__ int                 g_ovf[MAX_E];                                // 12.8MB
__device__ unsigned            g_ovf_n;

// ---- packed f32x2 helpers ----
#define PACK2F(d, x)    asm("mov.b64 %0, {%1, %1};" : "=l"(d) : "r"(__float_as_uint(x)))
#define FMA2(acc, a, b) asm("fma.rn.f32x2 %0, %1, %2, %0;" : "+l"(acc) : "l"(a), "l"(b))

// smem layout for MLP: bf16 tiles, k-major [k][n], n-pitch padded to 72 bf16 = 144B
#define PITCH     144
#define OFF_W1HI  0
#define OFF_W1LO  73728
#define OFF_W2HI  147456
#define OFF_W2LO  156672
#define SMEM_TOTAL 165888

__device__ __forceinline__ unsigned smem_u32(const void* p) {
  unsigned a;
  asm("{ .reg .u64 t; cvta.to.shared.u64 t, %1; cvt.u32.u64 %0, t; }" : "=r"(a) : "l"(p));
  return a;
}
__device__ __forceinline__ void split2(float x, float y, unsigned &hi, unsigned &lo) {
  asm("cvt.rn.bf16x2.f32 %0, %1, %2;" : "=r"(hi) : "f"(y), "f"(x));
  float hx = __uint_as_float(hi << 16);
  float hy = __uint_as_float(hi & 0xFFFF0000u);
  asm("cvt.rn.bf16x2.f32 %0, %1, %2;" : "=r"(lo) : "f"(y - hy), "f"(x - hx));
}
__device__ __forceinline__ void ldmat4t(unsigned &r0, unsigned &r1, unsigned &r2,
                                        unsigned &r3, unsigned addr) {
  asm volatile("ldmatrix.sync.aligned.m8n8.x4.trans.shared.b16 {%0,%1,%2,%3}, [%4];"
               : "=r"(r0), "=r"(r1), "=r"(r2), "=r"(r3) : "r"(addr));
}
__device__ __forceinline__ void mma16816(float4 &c, unsigned a0, unsigned a1,
                                         unsigned a2, unsigned a3,
                                         unsigned b0, unsigned b1) {
  asm volatile("mma.sync.aligned.m16n8k16.row.col.f32.bf16.bf16.f32 "
               "{%0,%1,%2,%3}, {%4,%5,%6,%7}, {%8,%9}, {%0,%1,%2,%3};"
               : "+f"(c.x), "+f"(c.y), "+f"(c.z), "+f"(c.w)
               : "r"(a0), "r"(a1), "r"(a2), "r"(a3), "r"(b0), "r"(b1));
}

// ================= fused MLP via HMMA bf16x3 (round-4, proven) ==============
__global__ __launch_bounds__(256) void mlp_hmma(
    const float* __restrict__ X,
    const float* __restrict__ W1, const float* __restrict__ b1,
    const float* __restrict__ W2, const float* __restrict__ b2)
{
  extern __shared__ unsigned char sm[];
  const unsigned sb = smem_u32(sm);
  const int tid  = threadIdx.x;
  const int warp = tid >> 5;
  const unsigned lane = tid & 31;
  const int g  = lane >> 2;
  const int c2 = (lane & 3) * 2;

  for (int i = tid; i < F_IN * 32; i += 256) {
    int k = i >> 5, pr = i & 31;
    float2 w = __ldg((const float2*)(W1 + k * 64 + pr * 2));
    unsigned hi, lo; split2(w.x, w.y, hi, lo);
    *(unsigned*)(sm + OFF_W1HI + k * PITCH + pr * 4) = hi;
    *(unsigned*)(sm + OFF_W1LO + k * PITCH + pr * 4) = lo;
  }
  for (int i = tid; i < HIDDEN * 32; i += 256) {
    int k = i >> 5, pr = i & 31;
    float2 w = __ldg((const float2*)(W2 + k * 64 + pr * 2));
    unsigned hi, lo; split2(w.x, w.y, hi, lo);
    *(unsigned*)(sm + OFF_W2HI + k * PITCH + pr * 4) = hi;
    *(unsigned*)(sm + OFF_W2LO + k * PITCH + pr * 4) = lo;
  }
  float2 b1p[8], b2p[8];
#pragma unroll
  for (int j = 0; j < 8; ++j) {
    b1p[j] = __ldg((const float2*)(b1 + 8 * j + c2));
    b2p[j] = __ldg((const float2*)(b2 + 8 * j + c2));
  }
  __syncthreads();

  const int mid = lane >> 3, mrow = lane & 7;
  const unsigned loff = (unsigned)(((mid & 1) * 8 + mrow) * PITCH + (mid >> 1) * 16);
  const unsigned bW1h = sb + OFF_W1HI + loff;
  const unsigned bW1l = sb + OFF_W1LO + loff;
  const unsigned bW2h = sb + OFF_W2HI + loff;
  const unsigned bW2l = sb + OFF_W2LO + loff;

  for (int blk = blockIdx.x; blk < NBLK; blk += gridDim.x) {
    const int r0 = blk * TM + warp * 16 + g;
    const int r1 = r0 + 8;
    const bool v0 = r0 < N_NODES, v1 = r1 < N_NODES;
    const float* px0 = X + (long long)r0 * F_IN + c2;
    const float* px1 = X + (long long)r1 * F_IN + c2;

    float4 acc[8];
#pragma unroll
    for (int j = 0; j < 8; ++j) acc[j] = make_float4(0.f, 0.f, 0.f, 0.f);

    const float2 z2 = make_float2(0.f, 0.f);
    float2 cx00 = v0 ? __ldg((const float2*)px0)       : z2;
    float2 cx01 = v0 ? __ldg((const float2*)(px0 + 8)) : z2;
    float2 cx10 = v1 ? __ldg((const float2*)px1)       : z2;
    float2 cx11 = v1 ? __ldg((const float2*)(px1 + 8)) : z2;

#pragma unroll 4
    for (int ks = 0; ks < 32; ++ks) {
      float2 n00 = z2, n01 = z2, n10 = z2, n11 = z2;
      if (ks < 31) {
        const float* q0 = px0 + (ks + 1) * 16;
        const float* q1 = px1 + (ks + 1) * 16;
        if (v0) { n00 = __ldg((const float2*)q0); n01 = __ldg((const float2*)(q0 + 8)); }
        if (v1) { n10 = __ldg((const float2*)q1); n11 = __ldg((const float2*)(q1 + 8)); }
      }
      unsigned aH0, aL0, aH1, aL1, aH2, aL2, aH3, aL3;
      split2(cx00.x, cx00.y, aH0, aL0);
      split2(cx10.x, cx10.y, aH1, aL1);
      split2(cx01.x, cx01.y, aH2, aL2);
      split2(cx11.x, cx11.y, aH3, aL3);

#pragma unroll
      for (int jj = 0; jj < 4; ++jj) {
        unsigned h0, h1, h2, h3, l0, l1, l2, l3;
        ldmat4t(h0, h1, h2, h3, bW1h + ks * (16 * PITCH) + jj * 32);
        ldmat4t(l0, l1, l2, l3, bW1l + ks * (16 * PITCH) + jj * 32);
        mma16816(acc[2 * jj],     aH0, aH1, aH2, aH3, h0, h1);
        mma16816(acc[2 * jj],     aH0, aH1, aH2, aH3, l0, l1);
        mma16816(acc[2 * jj],     aL0, aL1, aL2, aL3, h0, h1);
        mma16816(acc[2 * jj + 1], aH0, aH1, aH2, aH3, h2, h3);
        mma16816(acc[2 * jj + 1], aH0, aH1, aH2, aH3, l2, l3);
        mma16816(acc[2 * jj + 1], aL0, aL1, aL2, aL3, h2, h3);
      }
      cx00 = n00; cx01 = n01; cx10 = n10; cx11 = n11;
    }

    unsigned A2h[4][4], A2l[4][4];
#pragma unroll
    for (int j = 0; j < 8; ++j) {
      float x = fmaxf(acc[j].x + b1p[j].x, 0.f);
      float y = fmaxf(acc[j].y + b1p[j].y, 0.f);
      float z = fmaxf(acc[j].z + b1p[j].x, 0.f);
      float w = fmaxf(acc[j].w + b1p[j].y, 0.f);
      unsigned h0, l0, h1, l1;
      split2(x, y, h0, l0);
      split2(z, w, h1, l1);
      int kk = j >> 1, s = j & 1;
      A2h[kk][2 * s] = h0; A2h[kk][2 * s + 1] = h1;
      A2l[kk][2 * s] = l0; A2l[kk][2 * s + 1] = l1;
    }

    float4 acc2[8];
#pragma unroll
    for (int j = 0; j < 8; ++j) acc2[j] = make_float4(0.f, 0.f, 0.f, 0.f);
#pragma unroll
    for (int kk = 0; kk < 4; ++kk) {
#pragma unroll
      for (int jj = 0; jj < 4; ++jj) {
        unsigned h0, h1, h2, h3, l0, l1, l2, l3;
        ldmat4t(h0, h1, h2, h3, bW2h + kk * (16 * PITCH) + jj * 32);
        ldmat4t(l0, l1, l2, l3, bW2l + kk * (16 * PITCH) + jj * 32);
        mma16816(acc2[2 * jj],     A2h[kk][0], A2h[kk][1], A2h[kk][2], A2h[kk][3], h0, h1);
        mma16816(acc2[2 * jj],     A2h[kk][0], A2h[kk][1], A2h[kk][2], A2h[kk][3], l0, l1);
        mma16816(acc2[2 * jj],     A2l[kk][0], A2l[kk][1], A2l[kk][2], A2l[kk][3], h0, h1);
        mma16816(acc2[2 * jj + 1], A2h[kk][0], A2h[kk][1], A2h[kk][2], A2h[kk][3], h2, h3);
        mma16816(acc2[2 * jj + 1], A2h[kk][0], A2h[kk][1], A2h[kk][2], A2h[kk][3], l2, l3);
        mma16816(acc2[2 * jj + 1], A2l[kk][0], A2l[kk][1], A2l[kk][2], A2l[kk][3], h2, h3);
      }
    }

#pragma unroll
    for (int j = 0; j < 8; ++j) {
      if (v0) {
        float2 o = make_float2(acc2[j].x + b2p[j].x, acc2[j].y + b2p[j].y);
        *(float2*)(g_logits + (long long)r0 * HIDDEN + 8 * j + c2) = o;
      }
      if (v1) {
        float2 o = make_float2(acc2[j].z + b2p[j].x, acc2[j].w + b2p[j].y);
        *(float2*)(g_logits + (long long)r1 * HIDDEN + 8 * j + c2) = o;
      }
    }
  }
}

// ================= scan-free padded-bucket CSR ===============================
__global__ void init_kernel()
{
  int i = blockIdx.x * blockDim.x + threadIdx.x;
  if (i < N_NODES) g_cnt[i] = 0u;
  if (i == 0) g_ovf_n = 0u;
}

__global__ void place_kernel(const int* __restrict__ rows,
                             const int* __restrict__ cols,
                             const float* __restrict__ vals, int E)
{
  int i = blockIdx.x * blockDim.x + threadIdx.x;
  if (i < E) {
    int r = rows[i];
    unsigned pos = atomicAdd(&g_cnt[r], 1u);
    if (pos < SLOTS) {
      g_meta[(long long)r * SLOTS + pos] =
          ((unsigned long long)__float_as_uint(vals[i]) << 32) | (unsigned)cols[i];
    } else {
      unsigned oi = atomicAdd(&g_ovf_n, 1u);
      g_ovf[oi] = i;
    }
  }
}

// warp per row: coalesced meta load, shfl broadcast, gather+FMA2, one store
__global__ __launch_bounds__(256) void spmm_kernel(float* __restrict__ out)
{
  const unsigned lane = threadIdx.x & 31;
  const int row = (blockIdx.x * blockDim.x + threadIdx.x) >> 5;
  if (row >= N_NODES) return;

  unsigned n = g_cnt[row];
  if (n > SLOTS) n = SLOTS;
  const unsigned long long* base = g_meta + (long long)row * SLOTS;

  unsigned long long m0 = (lane < n)      ? base[lane]      : 0ULL;
  unsigned long long m1 = (lane + 32 < n) ? base[lane + 32] : 0ULL;

  unsigned long long accA = 0ULL, accB = 0ULL;
  const int n0 = (n < 32u) ? (int)n : 32;

#pragma unroll 4
  for (int e = 0; e < n0; ++e) {
    unsigned long long me = __shfl_sync(0xFFFFFFFFu, m0, e);
    unsigned c = (unsigned)me;
    float v = __uint_as_float((unsigned)(me >> 32));
    unsigned long long p = *(const unsigned long long*)(g_logits + (long long)c * HIDDEN + 2 * lane);
    unsigned long long vv; PACK2F(vv, v);
    if (e & 1) { FMA2(accB, p, vv); } else { FMA2(accA, p, vv); }
  }
  const int n1 = (int)n - 32;
#pragma unroll 4
  for (int e = 0; e < n1; ++e) {
    unsigned long long me = __shfl_sync(0xFFFFFFFFu, m1, e);
    unsigned c = (unsigned)me;
    float v = __uint_as_float((unsigned)(me >> 32));
    unsigned long long p = *(const unsigned long long*)(g_logits + (long long)c * HIDDEN + 2 * lane);
    unsigned long long vv; PACK2F(vv, v);
    if (e & 1) { FMA2(accB, p, vv); } else { FMA2(accA, p, vv); }
  }

  unsigned a_lo, a_hi, b_lo, b_hi;
  asm("mov.b64 {%0, %1}, %2;" : "=r"(a_lo), "=r"(a_hi) : "l"(accA));
  asm("mov.b64 {%0, %1}, %2;" : "=r"(b_lo), "=r"(b_hi) : "l"(accB));
  float2 res;
  res.x = __uint_as_float(a_lo) + __uint_as_float(b_lo);
  res.y = __uint_as_float(a_hi) + __uint_as_float(b_hi);
  *(float2*)(out + (long long)row * HIDDEN + 2 * lane) = res;
}

// exact fallback for rows with degree > SLOTS (statistically empty)
__global__ void ovf_kernel(const int* __restrict__ rows, const int* __restrict__ cols,
                           const float* __restrict__ vals, float* __restrict__ out)
{
  const unsigned n = g_ovf_n;
  const int stride = gridDim.x * blockDim.x;
  for (unsigned j = blockIdx.x * blockDim.x + threadIdx.x; j < n; j += stride) {
    int i = g_ovf[j];
    int r = rows[i], c = cols[i];
    float v = vals[i];
#pragma unroll
    for (int k = 0; k < 16; ++k) {
      const float4 p = *(const float4*)(g_logits + (long long)c * HIDDEN + k * 4);
      float* dst = out + (long long)r * HIDDEN + k * 4;
      asm volatile("red.global.add.v4.f32 [%0], {%1, %2, %3, %4};"
                   :: "l"(dst), "f"(p.x * v), "f"(p.y * v), "f"(p.z * v), "f"(p.w * v)
                   : "memory");
    }
  }
}

// ================= launch ====================================================
extern "C" void kernel_launch(void* const* d_in, const int* in_sizes, int n_in,
                              void* d_out, int out_size)
{
  const float* X     = (const float*)d_in[0];
  const int*   erows = (const int*)  d_in[1];
  const int*   ecols = (const int*)  d_in[2];
  const float* evals = (const float*)d_in[3];
  const float* W1    = (const float*)d_in[4];
  const float* b1    = (const float*)d_in[5];
  const float* W2    = (const float*)d_in[6];
  const float* b2    = (const float*)d_in[7];
  float* out = (float*)d_out;
  const int E = in_sizes[1];

  cudaFuncSetAttribute(mlp_hmma, cudaFuncAttributeMaxDynamicSharedMemorySize, SMEM_TOTAL);

  init_kernel<<<(N_NODES + 255) / 256, 256>>>();
  place_kernel<<<(E + 255) / 256, 256>>>(erows, ecols, evals, E);
  mlp_hmma<<<148, 256, SMEM_TOTAL>>>(X, W1, b1, W2, b2);
  spmm_kernel<<<(N_NODES * 32 + 255) / 256, 256>>>(out);
  ovf_kernel<<<64, 256>>>(erows, ecols, evals, out);
}